// round 16
// baseline (speedup 1.0000x reference)
#include <cuda_runtime.h>
#include <cuda_fp16.h>
#include <math.h>
#include <stdint.h>

// Problem constants (fixed by setup_inputs)
#define NBLK  100000
#define NF    1000
#define KF    100
#define DH    512
#define DSEM  768
#define DSTR  256
#define DSH   256
#define DPR   256
#define NPROJ 100

// ---------------- scratch (device globals; no allocation allowed) ----------
__device__ __half g_big[(size_t)NBLK * 1024];   // fp16 A_cat
__device__ __half g_h1h[(size_t)NBLK * DH];     // h1 / h_blk-copy fp16
__device__ __half g_m  [(size_t)NBLK * DH];     // GCN pre-aggregation (fp16)
__device__ float  g_wc [1024 * DH];             // Wc = W_fusion @ W_g1 (fp32)
__device__ float  g_bc [DH];                    // bc = b_fusion @ W_g1
__device__ __half g_wf[DH * 1024];              // Wc^T fp16 [DH][1024]
__device__ __half g_w2[DH * DH];                // W_g2^T fp16
__device__ __half g_wa[DH * DH];                // W_att^T fp16
__device__ float g_scores[NBLK];
__device__ float g_t1[NF * DSH];
__device__ float g_t2[NF * DPR];
__device__ float g_ortho;

__device__ __forceinline__ uint32_t pack2h(float a, float b) {
    __half2 h = __floats2half2_rn(a, b);
    return *(uint32_t*)&h;
}

__device__ __forceinline__ void cpasync16(uint32_t smem_addr, const void* gptr, int src_sz) {
    asm volatile("cp.async.cg.shared.global [%0], [%1], 16, %2;\n"
                 :: "r"(smem_addr), "l"(gptr), "r"(src_sz));
}
__device__ __forceinline__ void cp_commit() {
    asm volatile("cp.async.commit_group;\n");
}
template<int NN>
__device__ __forceinline__ void cp_wait() {
    asm volatile("cp.async.wait_group %0;\n" :: "n"(NN));
}

__device__ __forceinline__ void ldsm_x4(uint32_t* r, uint32_t addr) {
    asm volatile("ldmatrix.sync.aligned.m8n8.x4.shared.b16 {%0,%1,%2,%3}, [%4];"
                 : "=r"(r[0]), "=r"(r[1]), "=r"(r[2]), "=r"(r[3]) : "r"(addr));
}

// =================== FP16 tensor-core GEMM, 3-stage cp.async + ldmatrix =====
// C[N,DO] = act( A[N,K](fp16, row-major) @ Bt[DO,K](fp16, row-major)^T )
// Tile 128x128x32, 3-stage ring, prefetch distance 2, uniform commit groups.
#define SRS_H    40
#define ROW_B    (SRS_H * 2)                     // 80 bytes
#define TILE_B   (128 * ROW_B)                   // 10240 B per matrix tile
#define STG_B    (2 * TILE_B)                    // A+B per stage = 20480 B
#define TG_SMEM  (3 * STG_B)                     // 61440 B

// ACT: 0 none, 1 relu, 2 tanh, 3 tanh+dot(context)->atomicAdd(scores) (no C)
// OUTH: store fp16 instead of fp32
template<int ACT, int OUTH>
__global__ void __launch_bounds__(256, 2)
tgemm_async(const __half* __restrict__ A, int lda,
            const __half* __restrict__ Bt, int ldb,   // [DO][K], ldb = K
            const float* __restrict__ bias,
            const float* __restrict__ ctx,            // ACT==3 only
            void* __restrict__ Cv,                    // C or scores (ACT==3)
            int N, int K, int DO)
{
    extern __shared__ __half smem[];

    const int tid  = threadIdx.x;
    const int row0 = blockIdx.y * 128;
    const int col0 = blockIdx.x * 128;

    const int warp = tid >> 5, lane = tid & 31;
    const int wm = warp & 1, wn = warp >> 1;
    const int gid = lane >> 2, tig = lane & 3;
    const int mbase = wm * 64, nbase = wn * 32;

    const int ar = tid >> 2;           // row base 0..63 (+64*i)
    const int cb = (tid & 3) * 16;     // byte offset within row data
    const int ch = (tid & 3) * 8;      // half offset within k-tile
    const uint32_t sm_base = (uint32_t)__cvta_generic_to_shared(smem);

    const uint32_t offA = (uint32_t)((lane & 15) * ROW_B + ((lane >> 4) << 4));
    const uint32_t offB = (uint32_t)(((lane & 7) + ((lane >> 4) << 3)) * ROW_B
                                     + (((lane >> 3) & 1) << 4));

    float c[4][4][4];
#pragma unroll
    for (int mi = 0; mi < 4; mi++)
#pragma unroll
        for (int ni = 0; ni < 4; ni++)
#pragma unroll
            for (int q = 0; q < 4; q++) c[mi][ni][q] = 0.f;

    const int nt = K >> 5;

    auto load_tile = [&](int kt, int s) {
        uint32_t sa = sm_base + (uint32_t)(s * STG_B);
        uint32_t sb = sa + (uint32_t)TILE_B;
        int k0 = kt << 5;
#pragma unroll
        for (int i = 0; i < 2; i++) {
            int rr = ar + i * 64;
            int gr = row0 + rr;
            int cr = gr < N ? gr : (N - 1);
            cpasync16(sa + (uint32_t)(rr * ROW_B) + cb,
                      A + (size_t)cr * lda + k0 + ch, gr < N ? 16 : 0);
        }
#pragma unroll
        for (int i = 0; i < 2; i++) {
            int rr = ar + i * 64;
            cpasync16(sb + (uint32_t)(rr * ROW_B) + cb,
                      Bt + (size_t)(col0 + rr) * ldb + k0 + ch, 16);
        }
        cp_commit();
    };

    load_tile(0, 0);
    if (nt > 1) load_tile(1, 1);
    else        cp_commit();

    int stage = 0;
    for (int kt = 0; kt < nt; kt++) {
        if (kt + 2 < nt) {
            int s2 = stage + 2; if (s2 >= 3) s2 -= 3;
            load_tile(kt + 2, s2);
        } else {
            cp_commit();
        }
        cp_wait<2>();
        __syncthreads();

        const uint32_t base = sm_base + (uint32_t)(stage * STG_B);
        const uint32_t saT = base + offA;
        const uint32_t sbT = base + (uint32_t)TILE_B + offB;

#pragma unroll
        for (int ks = 0; ks < 2; ks++) {
            const uint32_t kkb = (uint32_t)(ks * 32);
            uint32_t a[4][4];
#pragma unroll
            for (int mi = 0; mi < 4; mi++)
                ldsm_x4(a[mi], saT + (uint32_t)((mbase + mi * 16) * ROW_B) + kkb);
            uint32_t b[4][2];
#pragma unroll
            for (int p = 0; p < 2; p++) {
                uint32_t r[4];
                ldsm_x4(r, sbT + (uint32_t)((nbase + p * 16) * ROW_B) + kkb);
                b[2 * p + 0][0] = r[0]; b[2 * p + 0][1] = r[1];
                b[2 * p + 1][0] = r[2]; b[2 * p + 1][1] = r[3];
            }
#pragma unroll
            for (int mi = 0; mi < 4; mi++)
#pragma unroll
                for (int ni = 0; ni < 4; ni++) {
                    asm volatile(
                        "mma.sync.aligned.m16n8k16.row.col.f32.f16.f16.f32 "
                        "{%0,%1,%2,%3}, {%4,%5,%6,%7}, {%8,%9}, {%0,%1,%2,%3};"
                        : "+f"(c[mi][ni][0]), "+f"(c[mi][ni][1]),
                          "+f"(c[mi][ni][2]), "+f"(c[mi][ni][3])
                        : "r"(a[mi][0]), "r"(a[mi][1]), "r"(a[mi][2]), "r"(a[mi][3]),
                          "r"(b[ni][0]), "r"(b[ni][1]));
                }
        }
        __syncthreads();
        stage = stage + 1; if (stage >= 3) stage = 0;
    }

    // ---- epilogue ----
    if (ACT == 3) {
        float* scores = (float*)Cv;
        float bb0[4], bb1[4], cx0[4], cx1[4];
#pragma unroll
        for (int ni = 0; ni < 4; ni++) {
            int cg = col0 + nbase + ni * 8 + 2 * tig;
            bb0[ni] = bias ? bias[cg] : 0.f;
            bb1[ni] = bias ? bias[cg + 1] : 0.f;
            cx0[ni] = ctx[cg];
            cx1[ni] = ctx[cg + 1];
        }
#pragma unroll
        for (int mi = 0; mi < 4; mi++) {
#pragma unroll
            for (int h = 0; h < 2; h++) {
                int r = row0 + mbase + mi * 16 + gid + h * 8;
                float d = 0.f;
#pragma unroll
                for (int ni = 0; ni < 4; ni++) {
                    d += tanhf(c[mi][ni][2 * h + 0] + bb0[ni]) * cx0[ni];
                    d += tanhf(c[mi][ni][2 * h + 1] + bb1[ni]) * cx1[ni];
                }
                d += __shfl_xor_sync(0xffffffffu, d, 1);
                d += __shfl_xor_sync(0xffffffffu, d, 2);
                if (tig == 0 && r < N) atomicAdd(&scores[r], d);
            }
        }
        return;
    }

    float*    Cf = (float*)Cv;
    uint32_t* Ch = (uint32_t*)Cv;
#pragma unroll
    for (int ni = 0; ni < 4; ni++) {
        int cg = col0 + nbase + ni * 8 + 2 * tig;
        float b0 = 0.f, b1 = 0.f;
        if (bias && cg < DO)     b0 = bias[cg];
        if (bias && cg + 1 < DO) b1 = bias[cg + 1];
#pragma unroll
        for (int mi = 0; mi < 4; mi++) {
            int rg = row0 + mbase + mi * 16 + gid;
#pragma unroll
            for (int h = 0; h < 2; h++) {
                int r = rg + h * 8;
                if (r >= N) continue;
                float v0 = c[mi][ni][2 * h + 0] + b0;
                float v1 = c[mi][ni][2 * h + 1] + b1;
                if (ACT == 1) { v0 = fmaxf(v0, 0.f); v1 = fmaxf(v1, 0.f); }
                if (ACT == 2) { v0 = tanhf(v0);      v1 = tanhf(v1); }
                if (cg + 1 < DO) {
                    if (OUTH) Ch[((size_t)r * DO + cg) >> 1] = pack2h(v0, v1);
                    else *(float2*)(Cf + (size_t)r * DO + cg) = make_float2(v0, v1);
                } else if (cg < DO) {
                    if (!OUTH) Cf[(size_t)r * DO + cg] = v0;
                }
            }
        }
    }
}

// =================== conversion passes ======================================
__global__ void cvt_transpose3_kernel(const float* __restrict__ in0,
                                      const float* __restrict__ in1,
                                      const float* __restrict__ in2,
                                      __half* __restrict__ out0,
                                      __half* __restrict__ out1,
                                      __half* __restrict__ out2)
{
    const int z = blockIdx.z;
    const int K = (z == 0) ? 1024 : DH;
    const float* in = (z == 0) ? in0 : (z == 1) ? in1 : in2;
    __half* out     = (z == 0) ? out0 : (z == 1) ? out1 : out2;

    int kb = blockIdx.y * 32, db = blockIdx.x * 32;
    if (kb >= K) return;

    __shared__ __half tile[32][33];
    int tx = threadIdx.x, ty = threadIdx.y;  // 32 x 8
#pragma unroll
    for (int i = 0; i < 4; i++) {
        int k = kb + ty + i * 8;
        tile[ty + i * 8][tx] = __float2half_rn(in[(size_t)k * DH + db + tx]);
    }
    __syncthreads();
#pragma unroll
    for (int i = 0; i < 4; i++) {
        int d = db + ty + i * 8;
        out[(size_t)d * K + kb + tx] = tile[tx][ty + i * 8];
    }
}

__global__ void cvt_concat_kernel(const float* __restrict__ hs,
                                  const float* __restrict__ es,
                                  __half* __restrict__ out)
{
    long i = (long)blockIdx.x * blockDim.x + threadIdx.x;  // float4 index
    long total = (long)NBLK * 256;
    if (i >= total) return;
    int r = (int)(i >> 8);
    int q = (int)(i & 255);
    float4 v;
    if (q < 192) v = *(const float4*)(hs + (size_t)r * DSEM + q * 4);
    else         v = *(const float4*)(es + (size_t)r * DSTR + (q - 192) * 4);
    uint2 t;
    t.x = pack2h(v.x, v.y);
    t.y = pack2h(v.z, v.w);
    *(uint2*)(out + i * 4) = t;
}

// bc[c] = sum_k b_fusion[k] * W_g1[k][c]
__global__ void bias_fold_kernel(const float* __restrict__ bf,
                                 const float* __restrict__ W1,
                                 float* __restrict__ bc)
{
    int c = blockIdx.x * blockDim.x + threadIdx.x;
    if (c >= DH) return;
    float acc = 0.f;
    for (int k = 0; k < DH; k++) acc += bf[k] * W1[(size_t)k * DH + c];
    bc[c] = acc;
}

// ---------------- GCN aggregation as a 5-point stencil ----------------------
__device__ __forceinline__ float deg_of(int p) {
    int d = 1;
    d += (p >= 1);
    d += (p >= 2);
    d += (p < KF - 1);
    d += (p < KF - 2);
    return (float)d;
}

template<int RELU, int MODE>
__global__ void gcn_agg_kernel(const __half* __restrict__ m,
                               const float* __restrict__ bias,
                               float* __restrict__ outf,
                               __half* __restrict__ outh,
                               float* __restrict__ scz)
{
    const int C4 = DH / 4;
    long idx = (long)blockIdx.x * blockDim.x + threadIdx.x;
    long total = (long)NBLK * C4;
    if (idx >= total) return;
    int i  = (int)(idx / C4);
    int c4 = (int)(idx % C4) * 4;
    int pos = i % KF;
    float di = rsqrtf(deg_of(pos));

    if (scz && c4 == 0) scz[i] = 0.f;

    float4 acc = make_float4(0.f, 0.f, 0.f, 0.f);
#pragma unroll
    for (int d = -2; d <= 2; d++) {
        int p = pos + d;
        if (p < 0 || p >= KF) continue;
        float w = di * rsqrtf(deg_of(p));
        uint2 hv = *(const uint2*)(m + (size_t)(i + d) * DH + c4);
        float2 lo = __half22float2(*(__half2*)&hv.x);
        float2 hi = __half22float2(*(__half2*)&hv.y);
        acc.x += w * lo.x; acc.y += w * lo.y;
        acc.z += w * hi.x; acc.w += w * hi.y;
    }
    float4 b = *(const float4*)(bias + c4);
    acc.x += b.x; acc.y += b.y; acc.z += b.z; acc.w += b.w;
    if (RELU) {
        acc.x = fmaxf(acc.x, 0.f); acc.y = fmaxf(acc.y, 0.f);
        acc.z = fmaxf(acc.z, 0.f); acc.w = fmaxf(acc.w, 0.f);
    }
    if (MODE == 0 || MODE == 2)
        *(float4*)(outf + (size_t)i * DH + c4) = acc;
    if (MODE == 1 || MODE == 2) {
        uint2 t;
        t.x = pack2h(acc.x, acc.y);
        t.y = pack2h(acc.z, acc.w);
        *(uint2*)(outh + (size_t)i * DH + c4) = t;
    }
}

// =================== fp32 SIMT 64x64 GEMM (head path) =======================
template<int ACT>
__global__ void sgemm64_dual_kernel(const float* __restrict__ A0,
                                    const float* __restrict__ A1,
                                    const float* __restrict__ B0,
                                    const float* __restrict__ B1,
                                    const float* __restrict__ bias0,
                                    const float* __restrict__ bias1,
                                    float* __restrict__ C0,
                                    float* __restrict__ C1,
                                    int N, int K, int DO)
{
    const float* A    = blockIdx.z ? A1 : A0;
    const float* B    = blockIdx.z ? B1 : B0;
    const float* bias = blockIdx.z ? bias1 : bias0;
    float*       C    = blockIdx.z ? C1 : C0;

    __shared__ float sA[16][72];
    __shared__ float sB[16][72];

    int tid  = threadIdx.x;            // 256
    int row0 = blockIdx.y * 64;
    int col0 = blockIdx.x * 64;

    float acc[4][4];
#pragma unroll
    for (int i = 0; i < 4; i++)
#pragma unroll
        for (int j = 0; j < 4; j++) acc[i][j] = 0.f;

    int ar = tid >> 2, ak = (tid & 3) * 4;
    int br = tid >> 4, bc = (tid & 15) * 4;
    int ty = tid >> 4, tx = tid & 15;

    for (int kt = 0; kt < K; kt += 16) {
        {
            int r = row0 + ar;
            float4 v = make_float4(0.f, 0.f, 0.f, 0.f);
            if (r < N) v = *(const float4*)(A + (size_t)r * K + kt + ak);
            sA[ak + 0][ar] = v.x;
            sA[ak + 1][ar] = v.y;
            sA[ak + 2][ar] = v.z;
            sA[ak + 3][ar] = v.w;
        }
        {
            int gc = col0 + bc;
            int kr = kt + br;
            float4 v = make_float4(0.f, 0.f, 0.f, 0.f);
            if (gc + 3 < DO) {
                v = *(const float4*)(B + (size_t)kr * DO + gc);
            } else {
                if (gc + 0 < DO) v.x = B[(size_t)kr * DO + gc + 0];
                if (gc + 1 < DO) v.y = B[(size_t)kr * DO + gc + 1];
                if (gc + 2 < DO) v.z = B[(size_t)kr * DO + gc + 2];
                if (gc + 3 < DO) v.w = B[(size_t)kr * DO + gc + 3];
            }
            *(float4*)&sB[br][bc] = v;
        }
        __syncthreads();

#pragma unroll
        for (int k = 0; k < 16; k++) {
            float a[4], b[4];
            *(float4*)&a[0] = *(const float4*)&sA[k][ty * 4];
            *(float4*)&b[0] = *(const float4*)&sB[k][tx * 4];
#pragma unroll
            for (int i = 0; i < 4; i++)
#pragma unroll
                for (int j = 0; j < 4; j++) acc[i][j] += a[i] * b[j];
        }
        __syncthreads();
    }

#pragma unroll
    for (int i = 0; i < 4; i++) {
        int r = row0 + ty * 4 + i;
        if (r >= N) continue;
#pragma unroll
        for (int j = 0; j < 4; j++) {
            int c = col0 + tx * 4 + j;
            if (c >= DO) continue;
            float v = acc[i][j];
            if (bias) v += bias[c];
            if (ACT == 1) v = fmaxf(v, 0.f);
            C[(size_t)r * DO + c] = v;
        }
    }
}

// ---------------- per-file segment softmax + attention pooling --------------
__global__ void segpool_kernel(const float* __restrict__ scores,
                               const float* __restrict__ h_blk,
                               float* __restrict__ alpha_out,
                               float* __restrict__ h_file)
{
    int f = blockIdx.x;
    int tid = threadIdx.x;  // 128 threads
    __shared__ float sred[128];
    __shared__ float salpha[KF];

    float s = (tid < KF) ? scores[f * KF + tid] : -1e30f;
    sred[tid] = s;
    __syncthreads();
    for (int o = 64; o > 0; o >>= 1) {
        if (tid < o) sred[tid] = fmaxf(sred[tid], sred[tid + o]);
        __syncthreads();
    }
    float mx = sred[0];
    __syncthreads();
    float e = (tid < KF) ? expf(s - mx) : 0.f;
    sred[tid] = e;
    __syncthreads();
    for (int o = 64; o > 0; o >>= 1) {
        if (tid < o) sred[tid] += sred[tid + o];
        __syncthreads();
    }
    float inv = 1.f / sred[0];
    if (tid < KF) {
        float a = e * inv;
        salpha[tid] = a;
        alpha_out[f * KF + tid] = a;
    }
    __syncthreads();

    const float* base = h_blk + (size_t)f * KF * DH;
    for (int c = tid; c < DH; c += 128) {
        float acc = 0.f;
#pragma unroll 4
        for (int p = 0; p < KF; p++) acc += salpha[p] * base[(size_t)p * DH + c];
        h_file[(size_t)f * DH + c] = acc;
    }
}

// ---------------- logit_bug GEMV --------------------------------------------
__global__ void bug_kernel(const float* __restrict__ h_file,
                           const float* __restrict__ W,
                           const float* __restrict__ b,
                           float* __restrict__ out)
{
    int gwarp = (int)((blockIdx.x * blockDim.x + threadIdx.x) >> 5);
    int lane  = threadIdx.x & 31;
    if (gwarp >= NF) return;
    const float* row = h_file + (size_t)gwarp * DH;
    float acc = 0.f;
    for (int c = lane; c < DH; c += 32) acc += row[c] * W[c];
#pragma unroll
    for (int o = 16; o > 0; o >>= 1) acc += __shfl_down_sync(0xffffffffu, acc, o);
    if (lane == 0) out[gwarp] = acc + b[0];
}

// ---------------- ortho loss (tiled GEMM-style) ------------------------------
__global__ void ortho_zero_kernel() { g_ortho = 0.f; }

// Each block: 64x64 (a,b) tile of M = zsh^T @ zpr; loop f in chunks of 16
// staged in smem; square + reduce + atomicAdd.
__global__ void ortho2_kernel(const float* __restrict__ zsh,
                              const float* __restrict__ zpr)
{
    __shared__ float sA[16][65];   // [f][a]
    __shared__ float sB[16][65];   // [f][b]
    __shared__ float sred[256];

    const int tid = threadIdx.x;          // 256
    const int a0 = blockIdx.x * 64;
    const int b0 = blockIdx.y * 64;
    const int ty = tid >> 4, tx = tid & 15;   // 16x16 threads, each 4x4 outputs

    float acc[4][4];
#pragma unroll
    for (int i = 0; i < 4; i++)
#pragma unroll
        for (int j = 0; j < 4; j++) acc[i][j] = 0.f;

    // loader: 256 threads cover 16 rows x 64 cols in 4 steps of f-rows
    const int lr = tid >> 6;      // 0..3 (f sub-row)
    const int lc = tid & 63;      // 0..63 (col)

    for (int f0 = 0; f0 < NF; f0 += 16) {
#pragma unroll
        for (int i = 0; i < 4; i++) {
            int f = f0 + lr + i * 4;
            float va = 0.f, vb = 0.f;
            if (f < NF) {
                va = zsh[(size_t)f * DSH + a0 + lc];
                vb = zpr[(size_t)f * DPR + b0 + lc];
            }
            sA[lr + i * 4][lc] = va;
            sB[lr + i * 4][lc] = vb;
        }
        __syncthreads();

#pragma unroll
        for (int k = 0; k < 16; k++) {
            float a[4], b[4];
#pragma unroll
            for (int i = 0; i < 4; i++) a[i] = sA[k][ty * 4 + i];
#pragma unroll
            for (int j = 0; j < 4; j++) b[j] = sB[k][tx * 4 + j];
#pragma unroll
            for (int i = 0; i < 4; i++)
#pragma unroll
                for (int j = 0; j < 4; j++) acc[i][j] += a[i] * b[j];
        }
        __syncthreads();
    }

    float ssq = 0.f;
#pragma unroll
    for (int i = 0; i < 4; i++)
#pragma unroll
        for (int j = 0; j < 4; j++) ssq += acc[i][j] * acc[i][j];

    sred[tid] = ssq;
    __syncthreads();
    for (int o = 128; o > 0; o >>= 1) {
        if (tid < o) sred[tid] += sred[tid + o];
        __syncthreads();
    }
    if (tid == 0) atomicAdd(&g_ortho, sred[0]);
}

__global__ void ortho_final_kernel(float* __restrict__ out) {
    out[0] = g_ortho / (float)(DSH * DPR);
}

// ---------------- launch -----------------------------------------------------
static inline dim3 gemm_grid(int n, int d) {
    return dim3((unsigned)((d + 127) / 128), (unsigned)((n + 127) / 128), 1);
}

extern "C" void kernel_launch(void* const* d_in, const int* in_sizes, int n_in,
                              void* d_out, int out_size)
{
    const float* h_sem    = (const float*)d_in[0];
    const float* e_struct = (const float*)d_in[1];
    const float* W_fusion = (const float*)d_in[2];
    const float* b_fusion = (const float*)d_in[3];
    const float* W_g1     = (const float*)d_in[4];
    const float* b_g1     = (const float*)d_in[5];
    const float* W_g2     = (const float*)d_in[6];
    const float* b_g2     = (const float*)d_in[7];
    const float* W_att    = (const float*)d_in[8];
    const float* b_att    = (const float*)d_in[9];
    const float* context  = (const float*)d_in[10];
    const float* W_sh1    = (const float*)d_in[11];
    const float* b_sh1    = (const float*)d_in[12];
    const float* W_sh2    = (const float*)d_in[13];
    const float* b_sh2    = (const float*)d_in[14];
    const float* W_pr1    = (const float*)d_in[15];
    const float* b_pr1    = (const float*)d_in[16];
    const float* W_pr2    = (const float*)d_in[17];
    const float* b_pr2    = (const float*)d_in[18];
    const float* W_dpr    = (const float*)d_in[19];
    const float* b_dpr    = (const float*)d_in[20];
    const float* W_bug    = (const float*)d_in[21];
    const float* b_bug    = (const float*)d_in[22];

    float* out     = (float*)d_out;
    float* o_hblk  = out;                                  // [NBLK, DH]
    float* o_alpha = o_hblk + (size_t)NBLK * DH;           // [NBLK]
    float* o_hfile = o_alpha + NBLK;                       // [NF, DH]
    float* o_zsh   = o_hfile + (size_t)NF * DH;            // [NF, DSH]
    float* o_zpr   = o_zsh   + (size_t)NF * DSH;           // [NF, DPR]
    float* o_log   = o_zpr   + (size_t)NF * DPR;           // [NF, NPROJ]
    float* o_bug   = o_log   + (size_t)NF * NPROJ;         // [NF]
    float* o_loss  = o_bug   + NF;                         // [1]

    float *p_wc, *p_bc, *p_scores, *p_t1, *p_t2;
    __half *p_big, *p_h1h, *p_m, *p_wf, *p_w2, *p_wa;
    cudaGetSymbolAddress((void**)&p_big, g_big);
    cudaGetSymbolAddress((void**)&p_h1h, g_h1h);
    cudaGetSymbolAddress((void**)&p_m, g_m);
    cudaGetSymbolAddress((void**)&p_wc, g_wc);
    cudaGetSymbolAddress((void**)&p_bc, g_bc);
    cudaGetSymbolAddress((void**)&p_wf, g_wf);
    cudaGetSymbolAddress((void**)&p_w2, g_w2);
    cudaGetSymbolAddress((void**)&p_wa, g_wa);
    cudaGetSymbolAddress((void**)&p_scores, g_scores);
    cudaGetSymbolAddress((void**)&p_t1, g_t1);
    cudaGetSymbolAddress((void**)&p_t2, g_t2);

    cudaFuncSetAttribute(tgemm_async<0,1>, cudaFuncAttributeMaxDynamicSharedMemorySize, TG_SMEM);
    cudaFuncSetAttribute(tgemm_async<3,0>, cudaFuncAttributeMaxDynamicSharedMemorySize, TG_SMEM);

    // 0a. Wc = W_fusion @ W_g1 (fp32, 1024x512), bc = b_fusion @ W_g1
    sgemm64_dual_kernel<0><<<dim3(DH / 64, 1024 / 64, 1), 256>>>(
        W_fusion, W_fusion, W_g1, W_g1, nullptr, nullptr, p_wc, p_wc,
        1024, DH, DH);
    bias_fold_kernel<<<2, 256>>>(b_fusion, W_g1, p_bc);

    // 0b. transpose-convert Wc, W_g2, W_att to fp16 [DO][K]
    {
        dim3 blk(32, 8);
        cvt_transpose3_kernel<<<dim3(DH / 32, 1024 / 32, 3), blk>>>(
            p_wc, W_g2, W_att, p_wf, p_w2, p_wa);
    }
    // 0c. fused input concat to fp16
    {
        long total = (long)NBLK * 256;
        cvt_concat_kernel<<<(unsigned)((total + 255) / 256), 256>>>(
            h_sem, e_struct, p_big);
    }

    // 1. m1(fp16) = [h_sem|e_struct] @ Wc + bc   (single K=1024 GEMM)
    tgemm_async<0,1><<<gemm_grid(NBLK, DH), 256, TG_SMEM>>>(
        p_big, 1024, p_wf, 1024, p_bc, nullptr, p_m, NBLK, 1024, DH);

    // 2. h1(fp16) = relu(agg(m1) + b_g1)
    {
        long total = (long)NBLK * (DH / 4);
        gcn_agg_kernel<1,1><<<(unsigned)((total + 255) / 256), 256>>>(
            p_m, b_g1, nullptr, p_h1h, nullptr);
    }

    // 3. m2(fp16) = h1 @ W_g2
    tgemm_async<0,1><<<gemm_grid(NBLK, DH), 256, TG_SMEM>>>(
        p_h1h, DH, p_w2, DH, nullptr, nullptr, p_m, NBLK, DH, DH);

    // 4. h_blk = agg(m2) + b_g2 -> fp32 output + fp16 copy; zero scores
    {
        long total = (long)NBLK * (DH / 4);
        gcn_agg_kernel<0,2><<<(unsigned)((total + 255) / 256), 256>>>(
            p_m, b_g2, o_hblk, p_h1h, p_scores);
    }

    // 5. scores = tanh(h_blk @ W_att + b_att) @ context  (fused epilogue)
    tgemm_async<3,0><<<gemm_grid(NBLK, DH), 256, TG_SMEM>>>(
        p_h1h, DH, p_wa, DH, b_att, context, p_scores, NBLK, DH, DH);

    // 6. segment softmax + pooling
    segpool_kernel<<<NF, 128>>>(p_scores, o_hblk, o_alpha, o_hfile);

    // 7-10. shared/project heads, fused in pairs via blockIdx.z
    sgemm64_dual_kernel<1><<<dim3(DSH / 64, (NF + 63) / 64, 2), 256>>>(
        o_hfile, o_hfile, W_sh1, W_pr1, b_sh1, b_pr1, p_t1, p_t2, NF, DH, DSH);
    sgemm64_dual_kernel<0><<<dim3(DSH / 64, (NF + 63) / 64, 2), 256>>>(
        p_t1, p_t2, W_sh2, W_pr2, b_sh2, b_pr2, o_zsh, o_zpr, NF, DSH, DSH);

    // 11. project-domain logits
    sgemm64_dual_kernel<0><<<dim3((NPROJ + 63) / 64, (NF + 63) / 64, 1), 256>>>(
        o_zpr, o_zpr, W_dpr, W_dpr, b_dpr, b_dpr, o_log, o_log, NF, DPR, NPROJ);

    // 12. bug logit
    bug_kernel<<<(NF * 32 + 255) / 256, 256>>>(o_hfile, W_bug, b_bug, o_bug);

    // 13. ortho loss (tiled)
    ortho_zero_kernel<<<1, 1>>>();
    ortho2_kernel<<<dim3(DSH / 64, DPR / 64), 256>>>(o_zsh, o_zpr);
    ortho_final_kernel<<<1, 1>>>(o_loss);
}

// round 17
// speedup vs baseline: 1.0378x; 1.0378x over previous
#include <cuda_runtime.h>
#include <cuda_fp16.h>
#include <math.h>
#include <stdint.h>

// Problem constants (fixed by setup_inputs)
#define NBLK  100000
#define NF    1000
#define KF    100
#define DH    512
#define DSEM  768
#define DSTR  256
#define DSH   256
#define DPR   256
#define NPROJ 100

// ---------------- scratch (device globals; no allocation allowed) ----------
__device__ __half g_big[(size_t)NBLK * 1024];   // fp16 A_cat
__device__ __half g_h1h[(size_t)NBLK * DH];     // h1 / h_blk-copy fp16
__device__ __half g_m  [(size_t)NBLK * DH];     // GCN pre-aggregation (fp16)
__device__ float  g_wc [1024 * DH];             // Wc = W_fusion @ W_g1 (fp32)
__device__ float  g_bc [DH];                    // bc = b_fusion @ W_g1
__device__ __half g_wf[DH * 1024];              // Wc^T fp16 [DH][1024]
__device__ __half g_w2[DH * DH];                // W_g2^T fp16
__device__ __half g_wa[DH * DH];                // W_att^T fp16
__device__ float g_scores[NBLK];
__device__ float g_t1[NF * DSH];
__device__ float g_t2[NF * DPR];
__device__ float g_ortho;

__device__ __forceinline__ uint32_t pack2h(float a, float b) {
    __half2 h = __floats2half2_rn(a, b);
    return *(uint32_t*)&h;
}

__device__ __forceinline__ void cpasync16(uint32_t smem_addr, const void* gptr, int src_sz) {
    asm volatile("cp.async.cg.shared.global [%0], [%1], 16, %2;\n"
                 :: "r"(smem_addr), "l"(gptr), "r"(src_sz));
}
__device__ __forceinline__ void cp_commit() {
    asm volatile("cp.async.commit_group;\n");
}
template<int NN>
__device__ __forceinline__ void cp_wait() {
    asm volatile("cp.async.wait_group %0;\n" :: "n"(NN));
}

__device__ __forceinline__ void ldsm_x4(uint32_t* r, uint32_t addr) {
    asm volatile("ldmatrix.sync.aligned.m8n8.x4.shared.b16 {%0,%1,%2,%3}, [%4];"
                 : "=r"(r[0]), "=r"(r[1]), "=r"(r[2]), "=r"(r[3]) : "r"(addr));
}

// =================== FP16 tensor-core GEMM, 3-stage cp.async + ldmatrix =====
// C[N,DO] = act( A[N,K](fp16, row-major) @ Bt[DO,K](fp16, row-major)^T )
// Tile 128x128x32, 3-stage ring, prefetch distance 2, uniform commit groups.
#define SRS_H    40
#define ROW_B    (SRS_H * 2)                     // 80 bytes
#define TILE_B   (128 * ROW_B)                   // 10240 B per matrix tile
#define STG_B    (2 * TILE_B)                    // A+B per stage = 20480 B
#define TG_SMEM  (3 * STG_B)                     // 61440 B

// ACT: 0 none, 1 relu, 2 tanh, 3 tanh+dot(context)->atomicAdd(scores) (no C)
// OUTH: store fp16 instead of fp32
template<int ACT, int OUTH>
__global__ void __launch_bounds__(256, 2)
tgemm_async(const __half* __restrict__ A, int lda,
            const __half* __restrict__ Bt, int ldb,   // [DO][K], ldb = K
            const float* __restrict__ bias,
            const float* __restrict__ ctx,            // ACT==3 only
            void* __restrict__ Cv,                    // C or scores (ACT==3)
            int N, int K, int DO)
{
    extern __shared__ __half smem[];

    const int tid  = threadIdx.x;
    const int row0 = blockIdx.y * 128;
    const int col0 = blockIdx.x * 128;

    const int warp = tid >> 5, lane = tid & 31;
    const int wm = warp & 1, wn = warp >> 1;
    const int gid = lane >> 2, tig = lane & 3;
    const int mbase = wm * 64, nbase = wn * 32;

    const int ar = tid >> 2;           // row base 0..63 (+64*i)
    const int cb = (tid & 3) * 16;     // byte offset within row data
    const int ch = (tid & 3) * 8;      // half offset within k-tile
    const uint32_t sm_base = (uint32_t)__cvta_generic_to_shared(smem);

    const uint32_t offA = (uint32_t)((lane & 15) * ROW_B + ((lane >> 4) << 4));
    const uint32_t offB = (uint32_t)(((lane & 7) + ((lane >> 4) << 3)) * ROW_B
                                     + (((lane >> 3) & 1) << 4));

    float c[4][4][4];
#pragma unroll
    for (int mi = 0; mi < 4; mi++)
#pragma unroll
        for (int ni = 0; ni < 4; ni++)
#pragma unroll
            for (int q = 0; q < 4; q++) c[mi][ni][q] = 0.f;

    const int nt = K >> 5;

    auto load_tile = [&](int kt, int s) {
        uint32_t sa = sm_base + (uint32_t)(s * STG_B);
        uint32_t sb = sa + (uint32_t)TILE_B;
        int k0 = kt << 5;
#pragma unroll
        for (int i = 0; i < 2; i++) {
            int rr = ar + i * 64;
            int gr = row0 + rr;
            int cr = gr < N ? gr : (N - 1);
            cpasync16(sa + (uint32_t)(rr * ROW_B) + cb,
                      A + (size_t)cr * lda + k0 + ch, gr < N ? 16 : 0);
        }
#pragma unroll
        for (int i = 0; i < 2; i++) {
            int rr = ar + i * 64;
            cpasync16(sb + (uint32_t)(rr * ROW_B) + cb,
                      Bt + (size_t)(col0 + rr) * ldb + k0 + ch, 16);
        }
        cp_commit();
    };

    load_tile(0, 0);
    if (nt > 1) load_tile(1, 1);
    else        cp_commit();

    int stage = 0;
    for (int kt = 0; kt < nt; kt++) {
        if (kt + 2 < nt) {
            int s2 = stage + 2; if (s2 >= 3) s2 -= 3;
            load_tile(kt + 2, s2);
        } else {
            cp_commit();
        }
        cp_wait<2>();
        __syncthreads();

        const uint32_t base = sm_base + (uint32_t)(stage * STG_B);
        const uint32_t saT = base + offA;
        const uint32_t sbT = base + (uint32_t)TILE_B + offB;

#pragma unroll
        for (int ks = 0; ks < 2; ks++) {
            const uint32_t kkb = (uint32_t)(ks * 32);
            uint32_t a[4][4];
#pragma unroll
            for (int mi = 0; mi < 4; mi++)
                ldsm_x4(a[mi], saT + (uint32_t)((mbase + mi * 16) * ROW_B) + kkb);
            uint32_t b[4][2];
#pragma unroll
            for (int p = 0; p < 2; p++) {
                uint32_t r[4];
                ldsm_x4(r, sbT + (uint32_t)((nbase + p * 16) * ROW_B) + kkb);
                b[2 * p + 0][0] = r[0]; b[2 * p + 0][1] = r[1];
                b[2 * p + 1][0] = r[2]; b[2 * p + 1][1] = r[3];
            }
#pragma unroll
            for (int mi = 0; mi < 4; mi++)
#pragma unroll
                for (int ni = 0; ni < 4; ni++) {
                    asm volatile(
                        "mma.sync.aligned.m16n8k16.row.col.f32.f16.f16.f32 "
                        "{%0,%1,%2,%3}, {%4,%5,%6,%7}, {%8,%9}, {%0,%1,%2,%3};"
                        : "+f"(c[mi][ni][0]), "+f"(c[mi][ni][1]),
                          "+f"(c[mi][ni][2]), "+f"(c[mi][ni][3])
                        : "r"(a[mi][0]), "r"(a[mi][1]), "r"(a[mi][2]), "r"(a[mi][3]),
                          "r"(b[ni][0]), "r"(b[ni][1]));
                }
        }
        __syncthreads();
        stage = stage + 1; if (stage >= 3) stage = 0;
    }

    // ---- epilogue ----
    if (ACT == 3) {
        float* scores = (float*)Cv;
        float bb0[4], bb1[4], cx0[4], cx1[4];
#pragma unroll
        for (int ni = 0; ni < 4; ni++) {
            int cg = col0 + nbase + ni * 8 + 2 * tig;
            bb0[ni] = bias ? bias[cg] : 0.f;
            bb1[ni] = bias ? bias[cg + 1] : 0.f;
            cx0[ni] = ctx[cg];
            cx1[ni] = ctx[cg + 1];
        }
#pragma unroll
        for (int mi = 0; mi < 4; mi++) {
#pragma unroll
            for (int h = 0; h < 2; h++) {
                int r = row0 + mbase + mi * 16 + gid + h * 8;
                float d = 0.f;
#pragma unroll
                for (int ni = 0; ni < 4; ni++) {
                    d += tanhf(c[mi][ni][2 * h + 0] + bb0[ni]) * cx0[ni];
                    d += tanhf(c[mi][ni][2 * h + 1] + bb1[ni]) * cx1[ni];
                }
                d += __shfl_xor_sync(0xffffffffu, d, 1);
                d += __shfl_xor_sync(0xffffffffu, d, 2);
                if (tig == 0 && r < N) atomicAdd(&scores[r], d);
            }
        }
        return;
    }

    float*    Cf = (float*)Cv;
    uint32_t* Ch = (uint32_t*)Cv;
#pragma unroll
    for (int ni = 0; ni < 4; ni++) {
        int cg = col0 + nbase + ni * 8 + 2 * tig;
        float b0 = 0.f, b1 = 0.f;
        if (bias && cg < DO)     b0 = bias[cg];
        if (bias && cg + 1 < DO) b1 = bias[cg + 1];
#pragma unroll
        for (int mi = 0; mi < 4; mi++) {
            int rg = row0 + mbase + mi * 16 + gid;
#pragma unroll
            for (int h = 0; h < 2; h++) {
                int r = rg + h * 8;
                if (r >= N) continue;
                float v0 = c[mi][ni][2 * h + 0] + b0;
                float v1 = c[mi][ni][2 * h + 1] + b1;
                if (ACT == 1) { v0 = fmaxf(v0, 0.f); v1 = fmaxf(v1, 0.f); }
                if (ACT == 2) { v0 = tanhf(v0);      v1 = tanhf(v1); }
                if (cg + 1 < DO) {
                    if (OUTH) Ch[((size_t)r * DO + cg) >> 1] = pack2h(v0, v1);
                    else *(float2*)(Cf + (size_t)r * DO + cg) = make_float2(v0, v1);
                } else if (cg < DO) {
                    if (!OUTH) Cf[(size_t)r * DO + cg] = v0;
                }
            }
        }
    }
}

// =================== conversion passes ======================================
__global__ void cvt_transpose3_kernel(const float* __restrict__ in0,
                                      const float* __restrict__ in1,
                                      const float* __restrict__ in2,
                                      __half* __restrict__ out0,
                                      __half* __restrict__ out1,
                                      __half* __restrict__ out2)
{
    const int z = blockIdx.z;
    const int K = (z == 0) ? 1024 : DH;
    const float* in = (z == 0) ? in0 : (z == 1) ? in1 : in2;
    __half* out     = (z == 0) ? out0 : (z == 1) ? out1 : out2;

    int kb = blockIdx.y * 32, db = blockIdx.x * 32;
    if (kb >= K) return;

    __shared__ __half tile[32][33];
    int tx = threadIdx.x, ty = threadIdx.y;  // 32 x 8
#pragma unroll
    for (int i = 0; i < 4; i++) {
        int k = kb + ty + i * 8;
        tile[ty + i * 8][tx] = __float2half_rn(in[(size_t)k * DH + db + tx]);
    }
    __syncthreads();
#pragma unroll
    for (int i = 0; i < 4; i++) {
        int d = db + ty + i * 8;
        out[(size_t)d * K + kb + tx] = tile[tx][ty + i * 8];
    }
}

__global__ void cvt_concat_kernel(const float* __restrict__ hs,
                                  const float* __restrict__ es,
                                  __half* __restrict__ out)
{
    long i = (long)blockIdx.x * blockDim.x + threadIdx.x;  // float4 index
    long total = (long)NBLK * 256;
    if (i >= total) return;
    int r = (int)(i >> 8);
    int q = (int)(i & 255);
    float4 v;
    if (q < 192) v = *(const float4*)(hs + (size_t)r * DSEM + q * 4);
    else         v = *(const float4*)(es + (size_t)r * DSTR + (q - 192) * 4);
    uint2 t;
    t.x = pack2h(v.x, v.y);
    t.y = pack2h(v.z, v.w);
    *(uint2*)(out + i * 4) = t;
}

// bc[c] = sum_k b_fusion[k] * W_g1[k][c]
__global__ void bias_fold_kernel(const float* __restrict__ bf,
                                 const float* __restrict__ W1,
                                 float* __restrict__ bc)
{
    int c = blockIdx.x * blockDim.x + threadIdx.x;
    if (c >= DH) return;
    float acc = 0.f;
    for (int k = 0; k < DH; k++) acc += bf[k] * W1[(size_t)k * DH + c];
    bc[c] = acc;
}

// ---------------- GCN aggregation as a 5-point stencil ----------------------
__device__ __forceinline__ float deg_of(int p) {
    int d = 1;
    d += (p >= 1);
    d += (p >= 2);
    d += (p < KF - 1);
    d += (p < KF - 2);
    return (float)d;
}

template<int RELU, int MODE>
__global__ void gcn_agg_kernel(const __half* __restrict__ m,
                               const float* __restrict__ bias,
                               float* __restrict__ outf,
                               __half* __restrict__ outh,
                               float* __restrict__ scz)
{
    const int C4 = DH / 4;
    long idx = (long)blockIdx.x * blockDim.x + threadIdx.x;
    long total = (long)NBLK * C4;
    if (idx >= total) return;
    int i  = (int)(idx / C4);
    int c4 = (int)(idx % C4) * 4;
    int pos = i % KF;
    float di = rsqrtf(deg_of(pos));

    if (scz && c4 == 0) scz[i] = 0.f;

    float4 acc = make_float4(0.f, 0.f, 0.f, 0.f);
#pragma unroll
    for (int d = -2; d <= 2; d++) {
        int p = pos + d;
        if (p < 0 || p >= KF) continue;
        float w = di * rsqrtf(deg_of(p));
        uint2 hv = *(const uint2*)(m + (size_t)(i + d) * DH + c4);
        float2 lo = __half22float2(*(__half2*)&hv.x);
        float2 hi = __half22float2(*(__half2*)&hv.y);
        acc.x += w * lo.x; acc.y += w * lo.y;
        acc.z += w * hi.x; acc.w += w * hi.y;
    }
    float4 b = *(const float4*)(bias + c4);
    acc.x += b.x; acc.y += b.y; acc.z += b.z; acc.w += b.w;
    if (RELU) {
        acc.x = fmaxf(acc.x, 0.f); acc.y = fmaxf(acc.y, 0.f);
        acc.z = fmaxf(acc.z, 0.f); acc.w = fmaxf(acc.w, 0.f);
    }
    if (MODE == 0 || MODE == 2)
        *(float4*)(outf + (size_t)i * DH + c4) = acc;
    if (MODE == 1 || MODE == 2) {
        uint2 t;
        t.x = pack2h(acc.x, acc.y);
        t.y = pack2h(acc.z, acc.w);
        *(uint2*)(outh + (size_t)i * DH + c4) = t;
    }
}

// =================== fp32 SIMT 64x64 GEMM (head path) =======================
template<int ACT>
__global__ void sgemm64_dual_kernel(const float* __restrict__ A0,
                                    const float* __restrict__ A1,
                                    const float* __restrict__ B0,
                                    const float* __restrict__ B1,
                                    const float* __restrict__ bias0,
                                    const float* __restrict__ bias1,
                                    float* __restrict__ C0,
                                    float* __restrict__ C1,
                                    int N, int K, int DO)
{
    const float* A    = blockIdx.z ? A1 : A0;
    const float* B    = blockIdx.z ? B1 : B0;
    const float* bias = blockIdx.z ? bias1 : bias0;
    float*       C    = blockIdx.z ? C1 : C0;

    __shared__ float sA[16][72];
    __shared__ float sB[16][72];

    int tid  = threadIdx.x;            // 256
    int row0 = blockIdx.y * 64;
    int col0 = blockIdx.x * 64;

    float acc[4][4];
#pragma unroll
    for (int i = 0; i < 4; i++)
#pragma unroll
        for (int j = 0; j < 4; j++) acc[i][j] = 0.f;

    int ar = tid >> 2, ak = (tid & 3) * 4;
    int br = tid >> 4, bc = (tid & 15) * 4;
    int ty = tid >> 4, tx = tid & 15;

    for (int kt = 0; kt < K; kt += 16) {
        {
            int r = row0 + ar;
            float4 v = make_float4(0.f, 0.f, 0.f, 0.f);
            if (r < N) v = *(const float4*)(A + (size_t)r * K + kt + ak);
            sA[ak + 0][ar] = v.x;
            sA[ak + 1][ar] = v.y;
            sA[ak + 2][ar] = v.z;
            sA[ak + 3][ar] = v.w;
        }
        {
            int gc = col0 + bc;
            int kr = kt + br;
            float4 v = make_float4(0.f, 0.f, 0.f, 0.f);
            if (gc + 3 < DO) {
                v = *(const float4*)(B + (size_t)kr * DO + gc);
            } else {
                if (gc + 0 < DO) v.x = B[(size_t)kr * DO + gc + 0];
                if (gc + 1 < DO) v.y = B[(size_t)kr * DO + gc + 1];
                if (gc + 2 < DO) v.z = B[(size_t)kr * DO + gc + 2];
                if (gc + 3 < DO) v.w = B[(size_t)kr * DO + gc + 3];
            }
            *(float4*)&sB[br][bc] = v;
        }
        __syncthreads();

#pragma unroll
        for (int k = 0; k < 16; k++) {
            float a[4], b[4];
            *(float4*)&a[0] = *(const float4*)&sA[k][ty * 4];
            *(float4*)&b[0] = *(const float4*)&sB[k][tx * 4];
#pragma unroll
            for (int i = 0; i < 4; i++)
#pragma unroll
                for (int j = 0; j < 4; j++) acc[i][j] += a[i] * b[j];
        }
        __syncthreads();
    }

#pragma unroll
    for (int i = 0; i < 4; i++) {
        int r = row0 + ty * 4 + i;
        if (r >= N) continue;
#pragma unroll
        for (int j = 0; j < 4; j++) {
            int c = col0 + tx * 4 + j;
            if (c >= DO) continue;
            float v = acc[i][j];
            if (bias) v += bias[c];
            if (ACT == 1) v = fmaxf(v, 0.f);
            C[(size_t)r * DO + c] = v;
        }
    }
}

// ---------------- per-file segment softmax + attention pooling --------------
__global__ void segpool_kernel(const float* __restrict__ scores,
                               const float* __restrict__ h_blk,
                               float* __restrict__ alpha_out,
                               float* __restrict__ h_file)
{
    int f = blockIdx.x;
    int tid = threadIdx.x;  // 256 threads
    __shared__ float sred[256];
    __shared__ float salpha[KF];

    float s = (tid < KF) ? scores[f * KF + tid] : -1e30f;
    sred[tid] = s;
    __syncthreads();
    for (int o = 128; o > 0; o >>= 1) {
        if (tid < o) sred[tid] = fmaxf(sred[tid], sred[tid + o]);
        __syncthreads();
    }
    float mx = sred[0];
    __syncthreads();
    float e = (tid < KF) ? expf(s - mx) : 0.f;
    sred[tid] = e;
    __syncthreads();
    for (int o = 128; o > 0; o >>= 1) {
        if (tid < o) sred[tid] += sred[tid + o];
        __syncthreads();
    }
    float inv = 1.f / sred[0];
    if (tid < KF) {
        float a = e * inv;
        salpha[tid] = a;
        alpha_out[f * KF + tid] = a;
    }
    __syncthreads();

    const float* base = h_blk + (size_t)f * KF * DH;
#pragma unroll
    for (int c = tid; c < DH; c += 256) {
        float acc = 0.f;
#pragma unroll 4
        for (int p = 0; p < KF; p++) acc += salpha[p] * base[(size_t)p * DH + c];
        h_file[(size_t)f * DH + c] = acc;
    }
}

// ---------------- logit_bug GEMV --------------------------------------------
__global__ void bug_kernel(const float* __restrict__ h_file,
                           const float* __restrict__ W,
                           const float* __restrict__ b,
                           float* __restrict__ out)
{
    int gwarp = (int)((blockIdx.x * blockDim.x + threadIdx.x) >> 5);
    int lane  = threadIdx.x & 31;
    if (gwarp >= NF) return;
    const float* row = h_file + (size_t)gwarp * DH;
    float acc = 0.f;
    for (int c = lane; c < DH; c += 32) acc += row[c] * W[c];
#pragma unroll
    for (int o = 16; o > 0; o >>= 1) acc += __shfl_down_sync(0xffffffffu, acc, o);
    if (lane == 0) out[gwarp] = acc + b[0];
}

// ---------------- ortho loss (R15 proven form) -------------------------------
__global__ void ortho_zero_kernel() { g_ortho = 0.f; }

__global__ void ortho_kernel(const float* __restrict__ zsh,
                             const float* __restrict__ zpr)
{
    int a = blockIdx.x;   // 0..DSH-1
    int b = threadIdx.x;  // 0..DPR-1
    float acc = 0.f;
    for (int f = 0; f < NF; f++)
        acc += zsh[(size_t)f * DSH + a] * zpr[(size_t)f * DPR + b];
    float v = acc * acc;
    __shared__ float sred[DPR];
    sred[b] = v;
    __syncthreads();
    for (int o = DPR / 2; o > 0; o >>= 1) {
        if (b < o) sred[b] += sred[b + o];
        __syncthreads();
    }
    if (b == 0) atomicAdd(&g_ortho, sred[0]);
}

__global__ void ortho_final_kernel(float* __restrict__ out) {
    out[0] = g_ortho / (float)(DSH * DPR);
}

// ---------------- launch -----------------------------------------------------
static inline dim3 gemm_grid(int n, int d) {
    return dim3((unsigned)((d + 127) / 128), (unsigned)((n + 127) / 128), 1);
}

extern "C" void kernel_launch(void* const* d_in, const int* in_sizes, int n_in,
                              void* d_out, int out_size)
{
    const float* h_sem    = (const float*)d_in[0];
    const float* e_struct = (const float*)d_in[1];
    const float* W_fusion = (const float*)d_in[2];
    const float* b_fusion = (const float*)d_in[3];
    const float* W_g1     = (const float*)d_in[4];
    const float* b_g1     = (const float*)d_in[5];
    const float* W_g2     = (const float*)d_in[6];
    const float* b_g2     = (const float*)d_in[7];
    const float* W_att    = (const float*)d_in[8];
    const float* b_att    = (const float*)d_in[9];
    const float* context  = (const float*)d_in[10];
    const float* W_sh1    = (const float*)d_in[11];
    const float* b_sh1    = (const float*)d_in[12];
    const float* W_sh2    = (const float*)d_in[13];
    const float* b_sh2    = (const float*)d_in[14];
    const float* W_pr1    = (const float*)d_in[15];
    const float* b_pr1    = (const float*)d_in[16];
    const float* W_pr2    = (const float*)d_in[17];
    const float* b_pr2    = (const float*)d_in[18];
    const float* W_dpr    = (const float*)d_in[19];
    const float* b_dpr    = (const float*)d_in[20];
    const float* W_bug    = (const float*)d_in[21];
    const float* b_bug    = (const float*)d_in[22];

    float* out     = (float*)d_out;
    float* o_hblk  = out;                                  // [NBLK, DH]
    float* o_alpha = o_hblk + (size_t)NBLK * DH;           // [NBLK]
    float* o_hfile = o_alpha + NBLK;                       // [NF, DH]
    float* o_zsh   = o_hfile + (size_t)NF * DH;            // [NF, DSH]
    float* o_zpr   = o_zsh   + (size_t)NF * DSH;           // [NF, DPR]
    float* o_log   = o_zpr   + (size_t)NF * DPR;           // [NF, NPROJ]
    float* o_bug   = o_log   + (size_t)NF * NPROJ;         // [NF]
    float* o_loss  = o_bug   + NF;                         // [1]

    float *p_wc, *p_bc, *p_scores, *p_t1, *p_t2;
    __half *p_big, *p_h1h, *p_m, *p_wf, *p_w2, *p_wa;
    cudaGetSymbolAddress((void**)&p_big, g_big);
    cudaGetSymbolAddress((void**)&p_h1h, g_h1h);
    cudaGetSymbolAddress((void**)&p_m, g_m);
    cudaGetSymbolAddress((void**)&p_wc, g_wc);
    cudaGetSymbolAddress((void**)&p_bc, g_bc);
    cudaGetSymbolAddress((void**)&p_wf, g_wf);
    cudaGetSymbolAddress((void**)&p_w2, g_w2);
    cudaGetSymbolAddress((void**)&p_wa, g_wa);
    cudaGetSymbolAddress((void**)&p_scores, g_scores);
    cudaGetSymbolAddress((void**)&p_t1, g_t1);
    cudaGetSymbolAddress((void**)&p_t2, g_t2);

    cudaFuncSetAttribute(tgemm_async<0,1>, cudaFuncAttributeMaxDynamicSharedMemorySize, TG_SMEM);
    cudaFuncSetAttribute(tgemm_async<3,0>, cudaFuncAttributeMaxDynamicSharedMemorySize, TG_SMEM);

    // 0a. Wc = W_fusion @ W_g1 (fp32, 1024x512), bc = b_fusion @ W_g1
    sgemm64_dual_kernel<0><<<dim3(DH / 64, 1024 / 64, 1), 256>>>(
        W_fusion, W_fusion, W_g1, W_g1, nullptr, nullptr, p_wc, p_wc,
        1024, DH, DH);
    bias_fold_kernel<<<2, 256>>>(b_fusion, W_g1, p_bc);

    // 0b. transpose-convert Wc, W_g2, W_att to fp16 [DO][K]
    {
        dim3 blk(32, 8);
        cvt_transpose3_kernel<<<dim3(DH / 32, 1024 / 32, 3), blk>>>(
            p_wc, W_g2, W_att, p_wf, p_w2, p_wa);
    }
    // 0c. fused input concat to fp16
    {
        long total = (long)NBLK * 256;
        cvt_concat_kernel<<<(unsigned)((total + 255) / 256), 256>>>(
            h_sem, e_struct, p_big);
    }

    // 1. m1(fp16) = [h_sem|e_struct] @ Wc + bc   (single K=1024 GEMM)
    tgemm_async<0,1><<<gemm_grid(NBLK, DH), 256, TG_SMEM>>>(
        p_big, 1024, p_wf, 1024, p_bc, nullptr, p_m, NBLK, 1024, DH);

    // 2. h1(fp16) = relu(agg(m1) + b_g1)
    {
        long total = (long)NBLK * (DH / 4);
        gcn_agg_kernel<1,1><<<(unsigned)((total + 255) / 256), 256>>>(
            p_m, b_g1, nullptr, p_h1h, nullptr);
    }

    // 3. m2(fp16) = h1 @ W_g2
    tgemm_async<0,1><<<gemm_grid(NBLK, DH), 256, TG_SMEM>>>(
        p_h1h, DH, p_w2, DH, nullptr, nullptr, p_m, NBLK, DH, DH);

    // 4. h_blk = agg(m2) + b_g2 -> fp32 output + fp16 copy; zero scores
    {
        long total = (long)NBLK * (DH / 4);
        gcn_agg_kernel<0,2><<<(unsigned)((total + 255) / 256), 256>>>(
            p_m, b_g2, o_hblk, p_h1h, p_scores);
    }

    // 5. scores = tanh(h_blk @ W_att + b_att) @ context  (fused epilogue)
    tgemm_async<3,0><<<gemm_grid(NBLK, DH), 256, TG_SMEM>>>(
        p_h1h, DH, p_wa, DH, b_att, context, p_scores, NBLK, DH, DH);

    // 6. segment softmax + pooling (256 threads/file)
    segpool_kernel<<<NF, 256>>>(p_scores, o_hblk, o_alpha, o_hfile);

    // 7-10. shared/project heads, fused in pairs via blockIdx.z
    sgemm64_dual_kernel<1><<<dim3(DSH / 64, (NF + 63) / 64, 2), 256>>>(
        o_hfile, o_hfile, W_sh1, W_pr1, b_sh1, b_pr1, p_t1, p_t2, NF, DH, DSH);
    sgemm64_dual_kernel<0><<<dim3(DSH / 64, (NF + 63) / 64, 2), 256>>>(
        p_t1, p_t2, W_sh2, W_pr2, b_sh2, b_pr2, o_zsh, o_zpr, NF, DSH, DSH);

    // 11. project-domain logits
    sgemm64_dual_kernel<0><<<dim3((NPROJ + 63) / 64, (NF + 63) / 64, 1), 256>>>(
        o_zpr, o_zpr, W_dpr, W_dpr, b_dpr, b_dpr, o_log, o_log, NF, DPR, NPROJ);

    // 12. bug logit
    bug_kernel<<<(NF * 32 + 255) / 256, 256>>>(o_hfile, W_bug, b_bug, o_bug);

    // 13. ortho loss
    ortho_zero_kernel<<<1, 1>>>();
    ortho_kernel<<<DSH, DPR>>>(o_zsh, o_zpr);
    ortho_final_kernel<<<1, 1>>>(o_loss);
}